// round 6
// baseline (speedup 1.0000x reference)
#include <cuda_runtime.h>
#include <cuda_bf16.h>
#include <cstdint>

// Problem constants
#define BATCH 2048
#define TT    609
#define NIN   5
#define HH    8
#define D_LSTM (TT * HH)     // 4872
#define N1    4096
#define N2    1024
#define N3    609            // == TT

// Scratch (no cudaMalloc allowed) ---------------------------------------------
__device__ float g_lstm_out[BATCH * D_LSTM];   // [2048, 4872] (tf32-rounded)
__device__ float g_act1[BATCH * N1];           // [2048, 4096] (tf32-rounded)
__device__ float g_act2[BATCH * N2];           // [2048, 1024] (tf32-rounded)
__device__ float g_w1t[N1 * D_LSTM];           // tf32-rounded W1
__device__ float g_w2t[N2 * N1];               // tf32-rounded W2
__device__ float g_w3t[N3 * N2];               // tf32-rounded W3

// ---------------------------------------------------------------------------
// tf32 rounding helpers
// ---------------------------------------------------------------------------
__device__ __forceinline__ float tf32r(float f) {
    uint32_t r;
    asm("cvt.rna.tf32.f32 %0, %1;" : "=r"(r) : "f"(f));
    return __uint_as_float(r);
}

__global__ void cvt_w_kernel(const float4* __restrict__ src, float4* __restrict__ dst, int n4)
{
    int i = blockIdx.x * blockDim.x + threadIdx.x;
    if (i < n4) {
        float4 v = src[i];
        v.x = tf32r(v.x); v.y = tf32r(v.y);
        v.z = tf32r(v.z); v.w = tf32r(v.w);
        dst[i] = v;
    }
}

// ---------------------------------------------------------------------------
// Fused 3-layer LSTM, 2 batch elements per 16-lane group (ILP x2).
// Within a 16-lane group: j = sub&7, half = sub>>3.
//   half==0 thread: gate rows j (i) and 16+j (g)
//   half==1 thread: gate rows 8+j (f) and 24+j (o)
// Weights shared across the two elements (same rows).
// ---------------------------------------------------------------------------

__device__ __forceinline__ float sigmoidf_fast(float v) {
    float e = __expf(-v);
    return __fdividef(1.0f, 1.0f + e);
}

template <int NI>
__device__ __forceinline__ void cell_step2(
    const float (&wA)[NI], const float (&wB)[NI],
    const float (&uA)[HH], const float (&uB)[HH],
    float bA, float bB,
    const float (&in0)[NI], const float (&in1)[NI],
    float (&h0)[HH], float (&h1)[HH],
    float& c0, float& c1, int half,
    float& hv0, float& hv1)
{
    float gA0 = bA, gB0 = bB, gA1 = bA, gB1 = bB;
#pragma unroll
    for (int i = 0; i < NI; i++) {
        gA0 = fmaf(wA[i], in0[i], gA0);
        gA1 = fmaf(wA[i], in1[i], gA1);
        gB0 = fmaf(wB[i], in0[i], gB0);
        gB1 = fmaf(wB[i], in1[i], gB1);
    }
#pragma unroll
    for (int k = 0; k < HH; k++) {
        gA0 = fmaf(uA[k], h0[k], gA0);
        gA1 = fmaf(uA[k], h1[k], gA1);
        gB0 = fmaf(uB[k], h0[k], gB0);
        gB1 = fmaf(uB[k], h1[k], gB1);
    }
    // gA: i (half0) / f (half1) -> sigmoid
    float va0 = sigmoidf_fast(gA0);
    float va1 = sigmoidf_fast(gA1);
    // gB: g (half0 -> tanh) / o (half1 -> sigmoid)
    float e0 = __expf(half ? -gB0 : (-2.0f * gB0));
    float e1 = __expf(half ? -gB1 : (-2.0f * gB1));
    float r0 = __fdividef(1.0f, 1.0f + e0);
    float r1 = __fdividef(1.0f, 1.0f + e1);
    float vb0 = half ? r0 : fmaf(2.0f, r0, -1.0f);
    float vb1 = half ? r1 : fmaf(2.0f, r1, -1.0f);

    // exchange across halves
    float pa0 = __shfl_xor_sync(0xffffffffu, va0, 8);
    float pa1 = __shfl_xor_sync(0xffffffffu, va1, 8);
    float pb0 = __shfl_xor_sync(0xffffffffu, vb0, 8);
    float pb1 = __shfl_xor_sync(0xffffffffu, vb1, 8);

    // valid in half0 lanes: i=va, g=vb, f=pa, o=pb
    c0 = fmaf(pa0, c0, va0 * vb0);
    c1 = fmaf(pa1, c1, va1 * vb1);
    float th0 = fmaf(2.0f, __fdividef(1.0f, 1.0f + __expf(-2.0f * c0)), -1.0f);
    float th1 = fmaf(2.0f, __fdividef(1.0f, 1.0f + __expf(-2.0f * c1)), -1.0f);
    hv0 = pb0 * th0;
    hv1 = pb1 * th1;

#pragma unroll
    for (int k = 0; k < HH; k++) {
        h0[k] = __shfl_sync(0xffffffffu, hv0, k, 16);
        h1[k] = __shfl_sync(0xffffffffu, hv1, k, 16);
    }
}

__global__ __launch_bounds__(64)
void lstm3_kernel(
    const float* __restrict__ x,
    const float* __restrict__ Wih1, const float* __restrict__ Whh1,
    const float* __restrict__ bih1, const float* __restrict__ bhh1,
    const float* __restrict__ Wih2, const float* __restrict__ Whh2,
    const float* __restrict__ bih2, const float* __restrict__ bhh2,
    const float* __restrict__ Wih3, const float* __restrict__ Whh3,
    const float* __restrict__ bih3, const float* __restrict__ bhh3,
    float* __restrict__ out)
{
    const int tid  = threadIdx.x;
    const int grp  = tid >> 4;            // 0..3
    const int sub  = tid & 15;
    const int j    = sub & 7;
    const int half = sub >> 3;
    const int b0   = (blockIdx.x * 4 + grp) * 2;  // elements b0, b0+1

    const int rowA = half * 8 + j;
    const int rowB = 16 + half * 8 + j;

    float wi1A[NIN], wi1B[NIN], uh1A[HH], uh1B[HH];
#pragma unroll
    for (int i = 0; i < NIN; i++) { wi1A[i] = Wih1[rowA * NIN + i]; wi1B[i] = Wih1[rowB * NIN + i]; }
#pragma unroll
    for (int k = 0; k < HH;  k++) { uh1A[k] = Whh1[rowA * HH + k]; uh1B[k] = Whh1[rowB * HH + k]; }
    float b1A = bih1[rowA] + bhh1[rowA];
    float b1B = bih1[rowB] + bhh1[rowB];

    float wi2A[HH], wi2B[HH], uh2A[HH], uh2B[HH];
#pragma unroll
    for (int k = 0; k < HH; k++) {
        wi2A[k] = Wih2[rowA * HH + k]; wi2B[k] = Wih2[rowB * HH + k];
        uh2A[k] = Whh2[rowA * HH + k]; uh2B[k] = Whh2[rowB * HH + k];
    }
    float b2A = bih2[rowA] + bhh2[rowA];
    float b2B = bih2[rowB] + bhh2[rowB];

    float wi3A[HH], wi3B[HH], uh3A[HH], uh3B[HH];
#pragma unroll
    for (int k = 0; k < HH; k++) {
        wi3A[k] = Wih3[rowA * HH + k]; wi3B[k] = Wih3[rowB * HH + k];
        uh3A[k] = Whh3[rowA * HH + k]; uh3B[k] = Whh3[rowB * HH + k];
    }
    float b3A = bih3[rowA] + bhh3[rowA];
    float b3B = bih3[rowB] + bhh3[rowB];

    float h1a[HH], h1b[HH], h2a[HH], h2b[HH], h3a[HH], h3b[HH];
#pragma unroll
    for (int k = 0; k < HH; k++) {
        h1a[k] = 0.f; h1b[k] = 0.f;
        h2a[k] = 0.f; h2b[k] = 0.f;
        h3a[k] = 0.f; h3b[k] = 0.f;
    }
    float c1a = 0.f, c1b = 0.f, c2a = 0.f, c2b = 0.f, c3a = 0.f, c3b = 0.f;

    const float* xr0 = x + (size_t)b0 * TT * NIN;
    const float* xr1 = xr0 + (size_t)TT * NIN;
    float* op0 = out + (size_t)b0 * D_LSTM;
    float* op1 = op0 + D_LSTM;

    float xn0[NIN], xn1[NIN];
#pragma unroll
    for (int i = 0; i < NIN; i++) { xn0[i] = xr0[i]; xn1[i] = xr1[i]; }

    for (int t = 0; t < TT; t++) {
        float xc0[NIN], xc1[NIN];
#pragma unroll
        for (int i = 0; i < NIN; i++) { xc0[i] = xn0[i]; xc1[i] = xn1[i]; }
        const int tn = (t + 1 < TT) ? (t + 1) : (TT - 1);
#pragma unroll
        for (int i = 0; i < NIN; i++) {
            xn0[i] = xr0[tn * NIN + i];
            xn1[i] = xr1[tn * NIN + i];
        }

        float d0, d1;
        cell_step2<NIN>(wi1A, wi1B, uh1A, uh1B, b1A, b1B, xc0, xc1, h1a, h1b, c1a, c1b, half, d0, d1);
        cell_step2<HH >(wi2A, wi2B, uh2A, uh2B, b2A, b2B, h1a, h1b, h2a, h2b, c2a, c2b, half, d0, d1);
        float hv0, hv1;
        cell_step2<HH >(wi3A, wi3B, uh3A, uh3B, b3A, b3B, h2a, h2b, h3a, h3b, c3a, c3b, half, hv0, hv1);

        if (half == 0) {
            op0[t * HH + j] = tf32r(hv0);   // pre-rounded for GEMM1
            op1[t * HH + j] = tf32r(hv1);
        }
    }
}

// ---------------------------------------------------------------------------
// tf32 tensor-core GEMM, cp.async double-buffered, 2x2 warps, frag dbl-buffer.
// All operands pre-rounded to tf32 in gmem -> NO cvt in mainloop.
// RELU=true layers store tf32-rounded outputs (they feed the next GEMM).
// ---------------------------------------------------------------------------

__device__ __forceinline__ void cp_async16(uint32_t dst, const void* src, int src_bytes) {
    asm volatile("cp.async.cg.shared.global [%0], [%1], 16, %2;\n"
                 :: "r"(dst), "l"(src), "r"(src_bytes));
}
__device__ __forceinline__ void cp_commit() {
    asm volatile("cp.async.commit_group;\n" ::: "memory");
}
template <int N>
__device__ __forceinline__ void cp_wait() {
    asm volatile("cp.async.wait_group %0;\n" :: "n"(N) : "memory");
}

__device__ __forceinline__ void mma_tf32(float (&c)[4], const uint32_t (&a)[4],
                                         const uint32_t (&b)[2]) {
    asm volatile(
        "mma.sync.aligned.m16n8k8.row.col.f32.tf32.tf32.f32 "
        "{%0,%1,%2,%3}, {%4,%5,%6,%7}, {%8,%9}, {%0,%1,%2,%3};"
        : "+f"(c[0]), "+f"(c[1]), "+f"(c[2]), "+f"(c[3])
        : "r"(a[0]), "r"(a[1]), "r"(a[2]), "r"(a[3]), "r"(b[0]), "r"(b[1]));
}

template <int BM, int BN, int BK, bool RELU>
__global__ __launch_bounds__(128, 2)
void gemm_tf32_v3(const float* __restrict__ A, const float* __restrict__ W,
                  const float* __restrict__ bias, float* __restrict__ C,
                  int M, int N, int K)
{
    constexpr int THREADS = 128;
    constexpr int WARPS_M = 2, WARPS_N = 2;
    constexpr int WM = BM / WARPS_M;       // 64
    constexpr int WN = BN / WARPS_N;       // 64 or 32
    constexpr int MT = WM / 16;            // 4
    constexpr int NT = WN / 8;             // 8 or 4
    constexpr int LD = BK + 4;             // smem row stride (words)

    extern __shared__ uint32_t sm[];
    uint32_t* As = sm;                     // [2][BM*LD]
    uint32_t* Bs = sm + 2 * BM * LD;       // [2][BN*LD]

    const int tid  = threadIdx.x;
    const int lane = tid & 31;
    const int warp = tid >> 5;
    const int wm   = warp / WARPS_N;
    const int wn   = warp % WARPS_N;
    const int g    = lane >> 2;
    const int t    = lane & 3;

    const int m0 = blockIdx.y * BM;
    const int n0 = blockIdx.x * BN;

    const uint32_t as_smem = (uint32_t)__cvta_generic_to_shared(As);
    const uint32_t bs_smem = (uint32_t)__cvta_generic_to_shared(Bs);

    float acc[MT][NT][4];
#pragma unroll
    for (int i = 0; i < MT; i++)
#pragma unroll
        for (int j = 0; j < NT; j++)
#pragma unroll
            for (int q = 0; q < 4; q++) acc[i][j][q] = 0.f;

    constexpr int KQ = BK / 4;
    constexpr int A_ITERS = BM * KQ / THREADS;
    constexpr int B_ITERS = BN * KQ / THREADS;

    auto load_tiles = [&](int k0, int stage) {
        const uint32_t a_base = as_smem + (uint32_t)stage * BM * LD * 4;
        const uint32_t b_base = bs_smem + (uint32_t)stage * BN * LD * 4;
#pragma unroll
        for (int r = 0; r < A_ITERS; r++) {
            const int idx = tid + r * THREADS;
            const int row = idx / KQ;
            const int kq  = idx % KQ;
            const int kg  = k0 + kq * 4;
            const bool ok = kg < K;
            const float* src = ok ? &A[(size_t)(m0 + row) * K + kg] : A;
            cp_async16(a_base + (row * LD + kq * 4) * 4, src, ok ? 16 : 0);
        }
#pragma unroll
        for (int r = 0; r < B_ITERS; r++) {
            const int idx = tid + r * THREADS;
            const int row = idx / KQ;
            const int kq  = idx % KQ;
            const int kg  = k0 + kq * 4;
            const bool ok = (n0 + row) < N && kg < K;
            const float* src = ok ? &W[(size_t)(n0 + row) * K + kg] : W;
            cp_async16(b_base + (row * LD + kq * 4) * 4, src, ok ? 16 : 0);
        }
        cp_commit();
    };

    const int nk = (K + BK - 1) / BK;

    load_tiles(0, 0);

    uint32_t af[2][MT][4], bf[2][NT][2];

    for (int it = 0; it < nk; it++) {
        const int cur = it & 1;
        if (it + 1 < nk) {
            load_tiles((it + 1) * BK, (it + 1) & 1);
            cp_wait<1>();
        } else {
            cp_wait<0>();
        }
        __syncthreads();

        const uint32_t* Ac = As + cur * BM * LD;
        const uint32_t* Bc = Bs + cur * BN * LD;

        auto ldfrag = [&](int kk, int buf) {
#pragma unroll
            for (int mt = 0; mt < MT; mt++) {
                const int r = wm * WM + mt * 16 + g;
                af[buf][mt][0] = Ac[(r    ) * LD + kk + t    ];
                af[buf][mt][1] = Ac[(r + 8) * LD + kk + t    ];
                af[buf][mt][2] = Ac[(r    ) * LD + kk + t + 4];
                af[buf][mt][3] = Ac[(r + 8) * LD + kk + t + 4];
            }
#pragma unroll
            for (int nt = 0; nt < NT; nt++) {
                const int cc = wn * WN + nt * 8 + g;
                bf[buf][nt][0] = Bc[cc * LD + kk + t    ];
                bf[buf][nt][1] = Bc[cc * LD + kk + t + 4];
            }
        };

        ldfrag(0, 0);
#pragma unroll
        for (int kk = 0; kk < BK; kk += 8) {
            const int cb = (kk >> 3) & 1;
            if (kk + 8 < BK)
                ldfrag(kk + 8, cb ^ 1);
#pragma unroll
            for (int mt = 0; mt < MT; mt++)
#pragma unroll
                for (int nt = 0; nt < NT; nt++)
                    mma_tf32(acc[mt][nt], af[cb][mt], bf[cb][nt]);
        }
        __syncthreads();
    }

    // ---- epilogue: bias (+relu), guarded stores ----
#pragma unroll
    for (int mt = 0; mt < MT; mt++) {
        const int r0 = m0 + wm * WM + mt * 16 + g;
        const int r1 = r0 + 8;
#pragma unroll
        for (int nt = 0; nt < NT; nt++) {
            const int cbase = n0 + wn * WN + nt * 8 + 2 * t;
#pragma unroll
            for (int q = 0; q < 2; q++) {
                const int cn = cbase + q;
                if (cn < N) {
                    const float bv = bias[cn];
                    float v0 = acc[mt][nt][q] + bv;
                    float v1 = acc[mt][nt][2 + q] + bv;
                    if (RELU) {
                        v0 = tf32r(fmaxf(v0, 0.f));   // feeds next tf32 GEMM
                        v1 = tf32r(fmaxf(v1, 0.f));
                    }
                    C[(size_t)r0 * N + cn] = v0;
                    C[(size_t)r1 * N + cn] = v1;
                }
            }
        }
    }
}

// ---------------------------------------------------------------------------
extern "C" void kernel_launch(void* const* d_in, const int* in_sizes, int n_in,
                              void* d_out, int out_size)
{
    const float* x    = (const float*)d_in[0];
    const float* Wih1 = (const float*)d_in[1];
    const float* Whh1 = (const float*)d_in[2];
    const float* bih1 = (const float*)d_in[3];
    const float* bhh1 = (const float*)d_in[4];
    const float* Wih2 = (const float*)d_in[5];
    const float* Whh2 = (const float*)d_in[6];
    const float* bih2 = (const float*)d_in[7];
    const float* bhh2 = (const float*)d_in[8];
    const float* Wih3 = (const float*)d_in[9];
    const float* Whh3 = (const float*)d_in[10];
    const float* bih3 = (const float*)d_in[11];
    const float* bhh3 = (const float*)d_in[12];
    const float* W1   = (const float*)d_in[13];
    const float* b1   = (const float*)d_in[14];
    const float* W2   = (const float*)d_in[15];
    const float* b2   = (const float*)d_in[16];
    const float* W3   = (const float*)d_in[17];
    const float* b3   = (const float*)d_in[18];
    float* out = (float*)d_out;

    float *lstm_o, *a1, *a2, *w1t, *w2t, *w3t;
    cudaGetSymbolAddress((void**)&lstm_o, g_lstm_out);
    cudaGetSymbolAddress((void**)&a1, g_act1);
    cudaGetSymbolAddress((void**)&a2, g_act2);
    cudaGetSymbolAddress((void**)&w1t, g_w1t);
    cudaGetSymbolAddress((void**)&w2t, g_w2t);
    cudaGetSymbolAddress((void**)&w3t, g_w3t);

    constexpr int LD = 36;
    constexpr int SMEM_128 = (2 * 128 * LD + 2 * 128 * LD) * 4;  // 73728
    constexpr int SMEM_64  = (2 * 128 * LD + 2 * 64 * LD) * 4;   // 55296

    static bool attr_done = false;
    if (!attr_done) {
        cudaFuncSetAttribute(gemm_tf32_v3<128, 128, 32, true>,
                             cudaFuncAttributeMaxDynamicSharedMemorySize, SMEM_128);
        cudaFuncSetAttribute(gemm_tf32_v3<128, 64, 32, true>,
                             cudaFuncAttributeMaxDynamicSharedMemorySize, SMEM_64);
        cudaFuncSetAttribute(gemm_tf32_v3<128, 64, 32, false>,
                             cudaFuncAttributeMaxDynamicSharedMemorySize, SMEM_64);
        attr_done = true;
    }

    // 0) pre-round weights to tf32 (removes all mainloop cvts)
    {
        const int n4_1 = N1 * D_LSTM / 4;
        const int n4_2 = N2 * N1 / 4;
        const int n4_3 = N3 * N2 / 4;
        cvt_w_kernel<<<(n4_1 + 255) / 256, 256>>>((const float4*)W1, (float4*)w1t, n4_1);
        cvt_w_kernel<<<(n4_2 + 255) / 256, 256>>>((const float4*)W2, (float4*)w2t, n4_2);
        cvt_w_kernel<<<(n4_3 + 255) / 256, 256>>>((const float4*)W3, (float4*)w3t, n4_3);
    }

    // 1) fused 3-layer LSTM: 2 elems per 16-lane group, 8 elems per 64-thr block
    lstm3_kernel<<<BATCH / 8, 64>>>(x,
        Wih1, Whh1, bih1, bhh1,
        Wih2, Whh2, bih2, bhh2,
        Wih3, Whh3, bih3, bhh3,
        lstm_o);

    // 2) MLP head (tf32, no mainloop cvt)
    {   // [2048,4872] x [4096,4872]^T -> relu -> [2048,4096]
        dim3 grid(N1 / 128, BATCH / 128);
        gemm_tf32_v3<128, 128, 32, true><<<grid, 128, SMEM_128>>>(
            lstm_o, w1t, b1, a1, BATCH, N1, D_LSTM);
    }
    {   // [2048,4096] x [1024,4096]^T -> relu -> [2048,1024]
        dim3 grid(N2 / 64, BATCH / 128);
        gemm_tf32_v3<128, 64, 32, true><<<grid, 128, SMEM_64>>>(
            a1, w2t, b2, a2, BATCH, N2, N1);
    }
    {   // [2048,1024] x [609,1024]^T -> [2048,609]
        dim3 grid((N3 + 63) / 64, BATCH / 128);
        gemm_tf32_v3<128, 64, 32, false><<<grid, 128, SMEM_64>>>(
            a2, w3t, b3, out, BATCH, N3, N2);
    }
}

// round 7
// speedup vs baseline: 1.5582x; 1.5582x over previous
#include <cuda_runtime.h>
#include <cuda_fp16.h>
#include <cstdint>

// Problem constants
#define BATCH 2048
#define TT    609
#define NIN   5
#define HH    8
#define D_LSTM (TT * HH)     // 4872
#define N1    4096
#define N2    1024
#define N3    609            // == TT

// Scratch (no cudaMalloc allowed) ---------------------------------------------
__device__ __half g_lstm_h[BATCH * D_LSTM];    // [2048, 4872] fp16
__device__ __half g_a1h[BATCH * N1];           // [2048, 4096] fp16
__device__ __half g_a2h[BATCH * N2];           // [2048, 1024] fp16
__device__ __half g_w1h[N1 * D_LSTM];          // fp16 W1
__device__ __half g_w2h[N2 * N1];              // fp16 W2
__device__ __half g_w3h[N3 * N2];              // fp16 W3

// ---------------------------------------------------------------------------
// weight fp32 -> fp16 conversion (once per launch, ~20us total)
// ---------------------------------------------------------------------------
__global__ void cvt_w_half(const float4* __restrict__ src, __half2* __restrict__ dst, int n4)
{
    int i = blockIdx.x * blockDim.x + threadIdx.x;
    if (i < n4) {
        float4 v = src[i];
        dst[2 * i + 0] = __floats2half2_rn(v.x, v.y);
        dst[2 * i + 1] = __floats2half2_rn(v.z, v.w);
    }
}

// ---------------------------------------------------------------------------
// Fused 3-layer LSTM, 2 batch elements per 16-lane group, split-accumulator
// gate chains (shorter serial FMA dependency). Output stored fp16 for GEMM1.
// ---------------------------------------------------------------------------

__device__ __forceinline__ float sigmoidf_fast(float v) {
    float e = __expf(-v);
    return __fdividef(1.0f, 1.0f + e);
}

template <int NI>
__device__ __forceinline__ void cell_step2(
    const float (&wA)[NI], const float (&wB)[NI],
    const float (&uA)[HH], const float (&uB)[HH],
    float bA, float bB,
    const float (&in0)[NI], const float (&in1)[NI],
    float (&h0)[HH], float (&h1)[HH],
    float& c0, float& c1, int half,
    float& hv0, float& hv1)
{
    // split accumulators: halve the serial FMA chain
    float gA0a = bA, gA0b = 0.f, gB0a = bB, gB0b = 0.f;
    float gA1a = bA, gA1b = 0.f, gB1a = bB, gB1b = 0.f;
#pragma unroll
    for (int i = 0; i < NI; i++) {
        if (i & 1) {
            gA0b = fmaf(wA[i], in0[i], gA0b);
            gA1b = fmaf(wA[i], in1[i], gA1b);
            gB0b = fmaf(wB[i], in0[i], gB0b);
            gB1b = fmaf(wB[i], in1[i], gB1b);
        } else {
            gA0a = fmaf(wA[i], in0[i], gA0a);
            gA1a = fmaf(wA[i], in1[i], gA1a);
            gB0a = fmaf(wB[i], in0[i], gB0a);
            gB1a = fmaf(wB[i], in1[i], gB1a);
        }
    }
#pragma unroll
    for (int k = 0; k < HH; k++) {
        if (k & 1) {
            gA0b = fmaf(uA[k], h0[k], gA0b);
            gA1b = fmaf(uA[k], h1[k], gA1b);
            gB0b = fmaf(uB[k], h0[k], gB0b);
            gB1b = fmaf(uB[k], h1[k], gB1b);
        } else {
            gA0a = fmaf(uA[k], h0[k], gA0a);
            gA1a = fmaf(uA[k], h1[k], gA1a);
            gB0a = fmaf(uB[k], h0[k], gB0a);
            gB1a = fmaf(uB[k], h1[k], gB1a);
        }
    }
    float gA0 = gA0a + gA0b, gB0 = gB0a + gB0b;
    float gA1 = gA1a + gA1b, gB1 = gB1a + gB1b;

    float va0 = sigmoidf_fast(gA0);
    float va1 = sigmoidf_fast(gA1);
    float e0 = __expf(half ? -gB0 : (-2.0f * gB0));
    float e1 = __expf(half ? -gB1 : (-2.0f * gB1));
    float r0 = __fdividef(1.0f, 1.0f + e0);
    float r1 = __fdividef(1.0f, 1.0f + e1);
    float vb0 = half ? r0 : fmaf(2.0f, r0, -1.0f);
    float vb1 = half ? r1 : fmaf(2.0f, r1, -1.0f);

    float pa0 = __shfl_xor_sync(0xffffffffu, va0, 8);
    float pa1 = __shfl_xor_sync(0xffffffffu, va1, 8);
    float pb0 = __shfl_xor_sync(0xffffffffu, vb0, 8);
    float pb1 = __shfl_xor_sync(0xffffffffu, vb1, 8);

    c0 = fmaf(pa0, c0, va0 * vb0);
    c1 = fmaf(pa1, c1, va1 * vb1);
    float th0 = fmaf(2.0f, __fdividef(1.0f, 1.0f + __expf(-2.0f * c0)), -1.0f);
    float th1 = fmaf(2.0f, __fdividef(1.0f, 1.0f + __expf(-2.0f * c1)), -1.0f);
    hv0 = pb0 * th0;
    hv1 = pb1 * th1;

#pragma unroll
    for (int k = 0; k < HH; k++) {
        h0[k] = __shfl_sync(0xffffffffu, hv0, k, 16);
        h1[k] = __shfl_sync(0xffffffffu, hv1, k, 16);
    }
}

__global__ __launch_bounds__(64)
void lstm3_kernel(
    const float* __restrict__ x,
    const float* __restrict__ Wih1, const float* __restrict__ Whh1,
    const float* __restrict__ bih1, const float* __restrict__ bhh1,
    const float* __restrict__ Wih2, const float* __restrict__ Whh2,
    const float* __restrict__ bih2, const float* __restrict__ bhh2,
    const float* __restrict__ Wih3, const float* __restrict__ Whh3,
    const float* __restrict__ bih3, const float* __restrict__ bhh3,
    __half* __restrict__ out)
{
    const int tid  = threadIdx.x;
    const int grp  = tid >> 4;
    const int sub  = tid & 15;
    const int j    = sub & 7;
    const int half = sub >> 3;
    const int b0   = (blockIdx.x * 4 + grp) * 2;

    const int rowA = half * 8 + j;
    const int rowB = 16 + half * 8 + j;

    float wi1A[NIN], wi1B[NIN], uh1A[HH], uh1B[HH];
#pragma unroll
    for (int i = 0; i < NIN; i++) { wi1A[i] = Wih1[rowA * NIN + i]; wi1B[i] = Wih1[rowB * NIN + i]; }
#pragma unroll
    for (int k = 0; k < HH;  k++) { uh1A[k] = Whh1[rowA * HH + k]; uh1B[k] = Whh1[rowB * HH + k]; }
    float b1A = bih1[rowA] + bhh1[rowA];
    float b1B = bih1[rowB] + bhh1[rowB];

    float wi2A[HH], wi2B[HH], uh2A[HH], uh2B[HH];
#pragma unroll
    for (int k = 0; k < HH; k++) {
        wi2A[k] = Wih2[rowA * HH + k]; wi2B[k] = Wih2[rowB * HH + k];
        uh2A[k] = Whh2[rowA * HH + k]; uh2B[k] = Whh2[rowB * HH + k];
    }
    float b2A = bih2[rowA] + bhh2[rowA];
    float b2B = bih2[rowB] + bhh2[rowB];

    float wi3A[HH], wi3B[HH], uh3A[HH], uh3B[HH];
#pragma unroll
    for (int k = 0; k < HH; k++) {
        wi3A[k] = Wih3[rowA * HH + k]; wi3B[k] = Wih3[rowB * HH + k];
        uh3A[k] = Whh3[rowA * HH + k]; uh3B[k] = Whh3[rowB * HH + k];
    }
    float b3A = bih3[rowA] + bhh3[rowA];
    float b3B = bih3[rowB] + bhh3[rowB];

    float h1a[HH], h1b[HH], h2a[HH], h2b[HH], h3a[HH], h3b[HH];
#pragma unroll
    for (int k = 0; k < HH; k++) {
        h1a[k] = 0.f; h1b[k] = 0.f;
        h2a[k] = 0.f; h2b[k] = 0.f;
        h3a[k] = 0.f; h3b[k] = 0.f;
    }
    float c1a = 0.f, c1b = 0.f, c2a = 0.f, c2b = 0.f, c3a = 0.f, c3b = 0.f;

    const float* xr0 = x + (size_t)b0 * TT * NIN;
    const float* xr1 = xr0 + (size_t)TT * NIN;
    __half* op0 = out + (size_t)b0 * D_LSTM;
    __half* op1 = op0 + D_LSTM;

    float xn0[NIN], xn1[NIN];
#pragma unroll
    for (int i = 0; i < NIN; i++) { xn0[i] = xr0[i]; xn1[i] = xr1[i]; }

    for (int t = 0; t < TT; t++) {
        float xc0[NIN], xc1[NIN];
#pragma unroll
        for (int i = 0; i < NIN; i++) { xc0[i] = xn0[i]; xc1[i] = xn1[i]; }
        const int tn = (t + 1 < TT) ? (t + 1) : (TT - 1);
#pragma unroll
        for (int i = 0; i < NIN; i++) {
            xn0[i] = xr0[tn * NIN + i];
            xn1[i] = xr1[tn * NIN + i];
        }

        float d0, d1;
        cell_step2<NIN>(wi1A, wi1B, uh1A, uh1B, b1A, b1B, xc0, xc1, h1a, h1b, c1a, c1b, half, d0, d1);
        cell_step2<HH >(wi2A, wi2B, uh2A, uh2B, b2A, b2B, h1a, h1b, h2a, h2b, c2a, c2b, half, d0, d1);
        float hv0, hv1;
        cell_step2<HH >(wi3A, wi3B, uh3A, uh3B, b3A, b3B, h2a, h2b, h3a, h3b, c3a, c3b, half, hv0, hv1);

        if (half == 0) {
            op0[t * HH + j] = __float2half_rn(hv0);
            op1[t * HH + j] = __float2half_rn(hv1);
        }
    }
}

// ---------------------------------------------------------------------------
// fp16 tensor-core GEMM (fp32 accumulate): C = A[M,K] @ W[N,K]^T + bias.
// mma.sync.m16n8k16.f32.f16.f16.f32 — 2x MACs/instr vs tf32 k8, same regs.
// cp.async double-buffered, 2x2 warps, fragment double-buffering.
// ---------------------------------------------------------------------------

__device__ __forceinline__ void cp_async16(uint32_t dst, const void* src, int src_bytes) {
    asm volatile("cp.async.cg.shared.global [%0], [%1], 16, %2;\n"
                 :: "r"(dst), "l"(src), "r"(src_bytes));
}
__device__ __forceinline__ void cp_commit() {
    asm volatile("cp.async.commit_group;\n" ::: "memory");
}
template <int N>
__device__ __forceinline__ void cp_wait() {
    asm volatile("cp.async.wait_group %0;\n" :: "n"(N) : "memory");
}

__device__ __forceinline__ void mma_f16(float (&c)[4], const uint32_t (&a)[4],
                                        const uint32_t (&b)[2]) {
    asm volatile(
        "mma.sync.aligned.m16n8k16.row.col.f32.f16.f16.f32 "
        "{%0,%1,%2,%3}, {%4,%5,%6,%7}, {%8,%9}, {%0,%1,%2,%3};"
        : "+f"(c[0]), "+f"(c[1]), "+f"(c[2]), "+f"(c[3])
        : "r"(a[0]), "r"(a[1]), "r"(a[2]), "r"(a[3]), "r"(b[0]), "r"(b[1]));
}

// OUT_HALF: store __half2 (feeds next fp16 GEMM); else fp32 with N guard.
template <int BM, int BN, bool RELU, bool OUT_HALF>
__global__ __launch_bounds__(128, 2)
void gemm_f16(const __half* __restrict__ A, const __half* __restrict__ W,
              const float* __restrict__ bias, void* __restrict__ Cv,
              int M, int N, int K)
{
    constexpr int BK = 64;                 // fp16 elements per K-slab
    constexpr int THREADS = 128;
    constexpr int WARPS_M = 2, WARPS_N = 2;
    constexpr int WM = BM / WARPS_M;       // 64
    constexpr int WN = BN / WARPS_N;       // 64 or 32
    constexpr int MT = WM / 16;            // 4
    constexpr int NT = WN / 8;             // 8 or 4
    constexpr int LDW = BK / 2 + 4;        // b32 words per row: 32 data + 4 pad

    extern __shared__ uint32_t sm[];
    uint32_t* As = sm;                     // [2][BM*LDW]
    uint32_t* Bs = sm + 2 * BM * LDW;      // [2][BN*LDW]

    const int tid  = threadIdx.x;
    const int lane = tid & 31;
    const int warp = tid >> 5;
    const int wm   = warp / WARPS_N;
    const int wn   = warp % WARPS_N;
    const int g    = lane >> 2;            // 0..7
    const int t    = lane & 3;             // 0..3

    const int m0 = blockIdx.y * BM;
    const int n0 = blockIdx.x * BN;

    const uint32_t as_smem = (uint32_t)__cvta_generic_to_shared(As);
    const uint32_t bs_smem = (uint32_t)__cvta_generic_to_shared(Bs);

    float acc[MT][NT][4];
#pragma unroll
    for (int i = 0; i < MT; i++)
#pragma unroll
        for (int j = 0; j < NT; j++)
#pragma unroll
            for (int q = 0; q < 4; q++) acc[i][j][q] = 0.f;

    constexpr int KQ = BK / 8;                     // 16B chunks per row = 8
    constexpr int A_ITERS = BM * KQ / THREADS;     // 8
    constexpr int B_ITERS = BN * KQ / THREADS;     // 8 or 4

    auto load_tiles = [&](int k0, int stage) {
        const uint32_t a_base = as_smem + (uint32_t)stage * BM * LDW * 4;
        const uint32_t b_base = bs_smem + (uint32_t)stage * BN * LDW * 4;
#pragma unroll
        for (int r = 0; r < A_ITERS; r++) {
            const int idx = tid + r * THREADS;
            const int row = idx / KQ;
            const int kq  = idx % KQ;
            const int kg  = k0 + kq * 8;
            const bool ok = kg < K;
            const __half* src = ok ? &A[(size_t)(m0 + row) * K + kg] : A;
            cp_async16(a_base + (row * LDW + kq * 4) * 4, src, ok ? 16 : 0);
        }
#pragma unroll
        for (int r = 0; r < B_ITERS; r++) {
            const int idx = tid + r * THREADS;
            const int row = idx / KQ;
            const int kq  = idx % KQ;
            const int kg  = k0 + kq * 8;
            const bool ok = (n0 + row) < N && kg < K;
            const __half* src = ok ? &W[(size_t)(n0 + row) * K + kg] : W;
            cp_async16(b_base + (row * LDW + kq * 4) * 4, src, ok ? 16 : 0);
        }
        cp_commit();
    };

    const int nk = (K + BK - 1) / BK;

    load_tiles(0, 0);

    uint32_t af[2][MT][4], bf[2][NT][2];

    for (int it = 0; it < nk; it++) {
        const int cur = it & 1;
        if (it + 1 < nk) {
            load_tiles((it + 1) * BK, (it + 1) & 1);
            cp_wait<1>();
        } else {
            cp_wait<0>();
        }
        __syncthreads();

        const uint32_t* Ac = As + cur * BM * LDW;
        const uint32_t* Bc = Bs + cur * BN * LDW;

        // k-step ks covers 16 fp16 = 8 b32 words
        auto ldfrag = [&](int ks, int buf) {
            const int wb = ks * 8;
#pragma unroll
            for (int mt = 0; mt < MT; mt++) {
                const int r = wm * WM + mt * 16 + g;
                af[buf][mt][0] = Ac[(r    ) * LDW + wb + t    ];
                af[buf][mt][1] = Ac[(r + 8) * LDW + wb + t    ];
                af[buf][mt][2] = Ac[(r    ) * LDW + wb + t + 4];
                af[buf][mt][3] = Ac[(r + 8) * LDW + wb + t + 4];
            }
#pragma unroll
            for (int nt = 0; nt < NT; nt++) {
                const int cc = wn * WN + nt * 8 + g;
                bf[buf][nt][0] = Bc[cc * LDW + wb + t    ];
                bf[buf][nt][1] = Bc[cc * LDW + wb + t + 4];
            }
        };

        ldfrag(0, 0);
#pragma unroll
        for (int ks = 0; ks < 4; ks++) {
            const int cb = ks & 1;
            if (ks + 1 < 4)
                ldfrag(ks + 1, cb ^ 1);
#pragma unroll
            for (int mt = 0; mt < MT; mt++)
#pragma unroll
                for (int nt = 0; nt < NT; nt++)
                    mma_f16(acc[mt][nt], af[cb][mt], bf[cb][nt]);
        }
        __syncthreads();
    }

    // ---- epilogue: bias (+relu) ----
#pragma unroll
    for (int mt = 0; mt < MT; mt++) {
        const int r0 = m0 + wm * WM + mt * 16 + g;
        const int r1 = r0 + 8;
#pragma unroll
        for (int nt = 0; nt < NT; nt++) {
            const int cbase = n0 + wn * WN + nt * 8 + 2 * t;
            if (OUT_HALF) {
                const float bv0 = bias[cbase], bv1 = bias[cbase + 1];
                float v00 = acc[mt][nt][0] + bv0;
                float v01 = acc[mt][nt][1] + bv1;
                float v10 = acc[mt][nt][2] + bv0;
                float v11 = acc[mt][nt][3] + bv1;
                if (RELU) {
                    v00 = fmaxf(v00, 0.f); v01 = fmaxf(v01, 0.f);
                    v10 = fmaxf(v10, 0.f); v11 = fmaxf(v11, 0.f);
                }
                __half2* C = (__half2*)Cv;
                C[((size_t)r0 * N + cbase) >> 1] = __floats2half2_rn(v00, v01);
                C[((size_t)r1 * N + cbase) >> 1] = __floats2half2_rn(v10, v11);
            } else {
                float* C = (float*)Cv;
#pragma unroll
                for (int q = 0; q < 2; q++) {
                    const int cn = cbase + q;
                    if (cn < N) {
                        const float bv = bias[cn];
                        float v0 = acc[mt][nt][q] + bv;
                        float v1 = acc[mt][nt][2 + q] + bv;
                        if (RELU) { v0 = fmaxf(v0, 0.f); v1 = fmaxf(v1, 0.f); }
                        C[(size_t)r0 * N + cn] = v0;
                        C[(size_t)r1 * N + cn] = v1;
                    }
                }
            }
        }
    }
}

// ---------------------------------------------------------------------------
extern "C" void kernel_launch(void* const* d_in, const int* in_sizes, int n_in,
                              void* d_out, int out_size)
{
    const float* x    = (const float*)d_in[0];
    const float* Wih1 = (const float*)d_in[1];
    const float* Whh1 = (const float*)d_in[2];
    const float* bih1 = (const float*)d_in[3];
    const float* bhh1 = (const float*)d_in[4];
    const float* Wih2 = (const float*)d_in[5];
    const float* Whh2 = (const float*)d_in[6];
    const float* bih2 = (const float*)d_in[7];
    const float* bhh2 = (const float*)d_in[8];
    const float* Wih3 = (const float*)d_in[9];
    const float* Whh3 = (const float*)d_in[10];
    const float* bih3 = (const float*)d_in[11];
    const float* bhh3 = (const float*)d_in[12];
    const float* W1   = (const float*)d_in[13];
    const float* b1   = (const float*)d_in[14];
    const float* W2   = (const float*)d_in[15];
    const float* b2   = (const float*)d_in[16];
    const float* W3   = (const float*)d_in[17];
    const float* b3   = (const float*)d_in[18];
    float* out = (float*)d_out;

    __half *lstm_h, *a1h, *a2h, *w1h, *w2h, *w3h;
    cudaGetSymbolAddress((void**)&lstm_h, g_lstm_h);
    cudaGetSymbolAddress((void**)&a1h, g_a1h);
    cudaGetSymbolAddress((void**)&a2h, g_a2h);
    cudaGetSymbolAddress((void**)&w1h, g_w1h);
    cudaGetSymbolAddress((void**)&w2h, g_w2h);
    cudaGetSymbolAddress((void**)&w3h, g_w3h);

    constexpr int LDW = 36;
    constexpr int SMEM_128 = (2 * 128 * LDW + 2 * 128 * LDW) * 4;  // 73728
    constexpr int SMEM_64  = (2 * 128 * LDW + 2 * 64 * LDW) * 4;   // 55296

    static bool attr_done = false;
    if (!attr_done) {
        cudaFuncSetAttribute(gemm_f16<128, 128, true, true>,
                             cudaFuncAttributeMaxDynamicSharedMemorySize, SMEM_128);
        cudaFuncSetAttribute(gemm_f16<128, 64, true, true>,
                             cudaFuncAttributeMaxDynamicSharedMemorySize, SMEM_64);
        cudaFuncSetAttribute(gemm_f16<128, 64, false, false>,
                             cudaFuncAttributeMaxDynamicSharedMemorySize, SMEM_64);
        attr_done = true;
    }

    // 0) pre-convert weights to fp16
    {
        const int n4_1 = N1 * D_LSTM / 4;
        const int n4_2 = N2 * N1 / 4;
        const int n4_3 = N3 * N2 / 4;
        cvt_w_half<<<(n4_1 + 255) / 256, 256>>>((const float4*)W1, (__half2*)w1h, n4_1);
        cvt_w_half<<<(n4_2 + 255) / 256, 256>>>((const float4*)W2, (__half2*)w2h, n4_2);
        cvt_w_half<<<(n4_3 + 255) / 256, 256>>>((const float4*)W3, (__half2*)w3h, n4_3);
    }

    // 1) fused 3-layer LSTM (fp16 output)
    lstm3_kernel<<<BATCH / 8, 64>>>(x,
        Wih1, Whh1, bih1, bhh1,
        Wih2, Whh2, bih2, bhh2,
        Wih3, Whh3, bih3, bhh3,
        lstm_h);

    // 2) MLP head (fp16 mma, fp32 accumulate)
    {   // [2048,4872] x [4096,4872]^T -> relu -> [2048,4096] fp16
        dim3 grid(N1 / 128, BATCH / 128);
        gemm_f16<128, 128, true, true><<<grid, 128, SMEM_128>>>(
            lstm_h, w1h, b1, a1h, BATCH, N1, D_LSTM);
    }
    {   // [2048,4096] x [1024,4096]^T -> relu -> [2048,1024] fp16
        dim3 grid(N2 / 64, BATCH / 128);
        gemm_f16<128, 64, true, true><<<grid, 128, SMEM_64>>>(
            a1h, w2h, b2, a2h, BATCH, N2, N1);
    }
    {   // [2048,1024] x [609,1024]^T -> [2048,609] fp32
        dim3 grid((N3 + 63) / 64, BATCH / 128);
        gemm_f16<128, 64, false, false><<<grid, 128, SMEM_64>>>(
            a2h, w3h, b3, out, BATCH, N3, N2);
    }
}

// round 8
// speedup vs baseline: 1.6959x; 1.0884x over previous
#include <cuda_runtime.h>
#include <cuda_fp16.h>
#include <cstdint>

// Problem constants
#define BATCH 2048
#define TT    609
#define NIN   5
#define HH    8
#define D_LSTM (TT * HH)     // 4872
#define N1    4096
#define N2    1024
#define N3    609            // == TT

// Scratch (no cudaMalloc allowed) ---------------------------------------------
__device__ __half g_lstm_h[BATCH * D_LSTM];    // [2048, 4872] fp16
__device__ __half g_a1h[BATCH * N1];           // [2048, 4096] fp16
__device__ __half g_a2h[BATCH * N2];           // [2048, 1024] fp16
__device__ __half g_w1h[N1 * D_LSTM];          // fp16 W1
__device__ __half g_w2h[N2 * N1];              // fp16 W2
__device__ __half g_w3h[N3 * N2];              // fp16 W3

// ---------------------------------------------------------------------------
// weight fp32 -> fp16 conversion (once per launch)
// ---------------------------------------------------------------------------
__global__ void cvt_w_half(const float4* __restrict__ src, __half2* __restrict__ dst, int n4)
{
    int i = blockIdx.x * blockDim.x + threadIdx.x;
    if (i < n4) {
        float4 v = src[i];
        dst[2 * i + 0] = __floats2half2_rn(v.x, v.y);
        dst[2 * i + 1] = __floats2half2_rn(v.z, v.w);
    }
}

// ---------------------------------------------------------------------------
// Fused 3-layer LSTM with LAYER SKEW (wavefront): iteration i computes
//   layer3 @ t=i-2, layer2 @ t=i-1, layer1 @ t=i  -- mutually independent,
// each reading the previous iteration's state. 2 batch elems per 16-lane
// group (ILP x2) -> 6 independent dependence chains per thread.
// ---------------------------------------------------------------------------

__device__ __forceinline__ float sigmoidf_fast(float v) {
    float e = __expf(-v);
    return __fdividef(1.0f, 1.0f + e);
}

template <int NI>
__device__ __forceinline__ void cell_step2(
    const float (&wA)[NI], const float (&wB)[NI],
    const float (&uA)[HH], const float (&uB)[HH],
    float bA, float bB,
    const float (&in0)[NI], const float (&in1)[NI],
    float (&h0)[HH], float (&h1)[HH],
    float& c0, float& c1, int half,
    float& hv0, float& hv1)
{
    float gA0a = bA, gA0b = 0.f, gB0a = bB, gB0b = 0.f;
    float gA1a = bA, gA1b = 0.f, gB1a = bB, gB1b = 0.f;
#pragma unroll
    for (int i = 0; i < NI; i++) {
        if (i & 1) {
            gA0b = fmaf(wA[i], in0[i], gA0b);
            gA1b = fmaf(wA[i], in1[i], gA1b);
            gB0b = fmaf(wB[i], in0[i], gB0b);
            gB1b = fmaf(wB[i], in1[i], gB1b);
        } else {
            gA0a = fmaf(wA[i], in0[i], gA0a);
            gA1a = fmaf(wA[i], in1[i], gA1a);
            gB0a = fmaf(wB[i], in0[i], gB0a);
            gB1a = fmaf(wB[i], in1[i], gB1a);
        }
    }
#pragma unroll
    for (int k = 0; k < HH; k++) {
        if (k & 1) {
            gA0b = fmaf(uA[k], h0[k], gA0b);
            gA1b = fmaf(uA[k], h1[k], gA1b);
            gB0b = fmaf(uB[k], h0[k], gB0b);
            gB1b = fmaf(uB[k], h1[k], gB1b);
        } else {
            gA0a = fmaf(uA[k], h0[k], gA0a);
            gA1a = fmaf(uA[k], h1[k], gA1a);
            gB0a = fmaf(uB[k], h0[k], gB0a);
            gB1a = fmaf(uB[k], h1[k], gB1a);
        }
    }
    float gA0 = gA0a + gA0b, gB0 = gB0a + gB0b;
    float gA1 = gA1a + gA1b, gB1 = gB1a + gB1b;

    float va0 = sigmoidf_fast(gA0);
    float va1 = sigmoidf_fast(gA1);
    float e0 = __expf(half ? -gB0 : (-2.0f * gB0));
    float e1 = __expf(half ? -gB1 : (-2.0f * gB1));
    float r0 = __fdividef(1.0f, 1.0f + e0);
    float r1 = __fdividef(1.0f, 1.0f + e1);
    float vb0 = half ? r0 : fmaf(2.0f, r0, -1.0f);
    float vb1 = half ? r1 : fmaf(2.0f, r1, -1.0f);

    float pa0 = __shfl_xor_sync(0xffffffffu, va0, 8);
    float pa1 = __shfl_xor_sync(0xffffffffu, va1, 8);
    float pb0 = __shfl_xor_sync(0xffffffffu, vb0, 8);
    float pb1 = __shfl_xor_sync(0xffffffffu, vb1, 8);

    c0 = fmaf(pa0, c0, va0 * vb0);
    c1 = fmaf(pa1, c1, va1 * vb1);
    float th0 = fmaf(2.0f, __fdividef(1.0f, 1.0f + __expf(-2.0f * c0)), -1.0f);
    float th1 = fmaf(2.0f, __fdividef(1.0f, 1.0f + __expf(-2.0f * c1)), -1.0f);
    hv0 = pb0 * th0;
    hv1 = pb1 * th1;

#pragma unroll
    for (int k = 0; k < HH; k++) {
        h0[k] = __shfl_sync(0xffffffffu, hv0, k, 16);
        h1[k] = __shfl_sync(0xffffffffu, hv1, k, 16);
    }
}

__global__ __launch_bounds__(32)
void lstm3_kernel(
    const float* __restrict__ x,
    const float* __restrict__ Wih1, const float* __restrict__ Whh1,
    const float* __restrict__ bih1, const float* __restrict__ bhh1,
    const float* __restrict__ Wih2, const float* __restrict__ Whh2,
    const float* __restrict__ bih2, const float* __restrict__ bhh2,
    const float* __restrict__ Wih3, const float* __restrict__ Whh3,
    const float* __restrict__ bih3, const float* __restrict__ bhh3,
    __half* __restrict__ out)
{
    const int tid  = threadIdx.x;
    const int grp  = tid >> 4;            // 0..1
    const int sub  = tid & 15;
    const int j    = sub & 7;
    const int half = sub >> 3;
    const int b0   = (blockIdx.x * 2 + grp) * 2;

    const int rowA = half * 8 + j;
    const int rowB = 16 + half * 8 + j;

    float wi1A[NIN], wi1B[NIN], uh1A[HH], uh1B[HH];
#pragma unroll
    for (int i = 0; i < NIN; i++) { wi1A[i] = Wih1[rowA * NIN + i]; wi1B[i] = Wih1[rowB * NIN + i]; }
#pragma unroll
    for (int k = 0; k < HH;  k++) { uh1A[k] = Whh1[rowA * HH + k]; uh1B[k] = Whh1[rowB * HH + k]; }
    float b1A = bih1[rowA] + bhh1[rowA];
    float b1B = bih1[rowB] + bhh1[rowB];

    float wi2A[HH], wi2B[HH], uh2A[HH], uh2B[HH];
#pragma unroll
    for (int k = 0; k < HH; k++) {
        wi2A[k] = Wih2[rowA * HH + k]; wi2B[k] = Wih2[rowB * HH + k];
        uh2A[k] = Whh2[rowA * HH + k]; uh2B[k] = Whh2[rowB * HH + k];
    }
    float b2A = bih2[rowA] + bhh2[rowA];
    float b2B = bih2[rowB] + bhh2[rowB];

    float wi3A[HH], wi3B[HH], uh3A[HH], uh3B[HH];
#pragma unroll
    for (int k = 0; k < HH; k++) {
        wi3A[k] = Wih3[rowA * HH + k]; wi3B[k] = Wih3[rowB * HH + k];
        uh3A[k] = Whh3[rowA * HH + k]; uh3B[k] = Whh3[rowB * HH + k];
    }
    float b3A = bih3[rowA] + bhh3[rowA];
    float b3B = bih3[rowB] + bhh3[rowB];

    float h1a[HH], h1b[HH], h2a[HH], h2b[HH], h3a[HH], h3b[HH];
#pragma unroll
    for (int k = 0; k < HH; k++) {
        h1a[k] = 0.f; h1b[k] = 0.f;
        h2a[k] = 0.f; h2b[k] = 0.f;
        h3a[k] = 0.f; h3b[k] = 0.f;
    }
    float c1a = 0.f, c1b = 0.f, c2a = 0.f, c2b = 0.f, c3a = 0.f, c3b = 0.f;

    const float* xr0 = x + (size_t)b0 * TT * NIN;
    const float* xr1 = xr0 + (size_t)TT * NIN;
    __half* op0 = out + (size_t)b0 * D_LSTM;
    __half* op1 = op0 + D_LSTM;

    float xn0[NIN], xn1[NIN];
#pragma unroll
    for (int i = 0; i < NIN; i++) { xn0[i] = xr0[i]; xn1[i] = xr1[i]; }

    float d0, d1, hv0, hv1;

    // helper lambdas for the three (independent) layer steps
    auto stepL1 = [&](const float (&xc0)[NIN], const float (&xc1)[NIN]) {
        cell_step2<NIN>(wi1A, wi1B, uh1A, uh1B, b1A, b1B, xc0, xc1,
                        h1a, h1b, c1a, c1b, half, d0, d1);
    };
    auto stepL2 = [&](const float (&i0)[HH], const float (&i1)[HH]) {
        cell_step2<HH>(wi2A, wi2B, uh2A, uh2B, b2A, b2B, i0, i1,
                       h2a, h2b, c2a, c2b, half, d0, d1);
    };
    auto stepL3 = [&](const float (&i0)[HH], const float (&i1)[HH]) {
        cell_step2<HH>(wi3A, wi3B, uh3A, uh3B, b3A, b3B, i0, i1,
                       h3a, h3b, c3a, c3b, half, hv0, hv1);
    };

    auto fetch_x = [&](int tn, float (&xc0)[NIN], float (&xc1)[NIN]) {
#pragma unroll
        for (int i = 0; i < NIN; i++) { xc0[i] = xn0[i]; xc1[i] = xn1[i]; }
#pragma unroll
        for (int i = 0; i < NIN; i++) {
            xn0[i] = xr0[tn * NIN + i];
            xn1[i] = xr1[tn * NIN + i];
        }
    };

    // ---- peeled prologue ----
    {   // i = 0: L1 only
        float xc0[NIN], xc1[NIN];
        fetch_x(1, xc0, xc1);
        stepL1(xc0, xc1);
    }
    {   // i = 1: L2 (reads h1 of t=0), then L1 (t=1)
        float xc0[NIN], xc1[NIN];
        fetch_x(2, xc0, xc1);
        // snapshot h1 BEFORE L1 updates it -> pass arrays directly; C sequencing
        stepL2(h1a, h1b);
        stepL1(xc0, xc1);
    }

    // ---- main loop: i = 2 .. TT-1 (branch-free body) ----
    for (int i = 2; i < TT; i++) {
        float xc0[NIN], xc1[NIN];
        const int tn = (i + 1 < TT) ? (i + 1) : (TT - 1);
        fetch_x(tn, xc0, xc1);

        stepL3(h2a, h2b);                 // t = i-2 (reads h2 pre-update)
        stepL2(h1a, h1b);                 // t = i-1 (reads h1 pre-update)
        stepL1(xc0, xc1);                 // t = i

        if (half == 0) {
            const int t = i - 2;
            op0[t * HH + j] = __float2half_rn(hv0);
            op1[t * HH + j] = __float2half_rn(hv1);
        }
    }

    // ---- peeled epilogue ----
    {   // i = TT: L3 (t=TT-2), L2 (t=TT-1)
        stepL3(h2a, h2b);
        stepL2(h1a, h1b);
        if (half == 0) {
            const int t = TT - 2;
            op0[t * HH + j] = __float2half_rn(hv0);
            op1[t * HH + j] = __float2half_rn(hv1);
        }
    }
    {   // i = TT+1: L3 (t=TT-1)
        stepL3(h2a, h2b);
        if (half == 0) {
            const int t = TT - 1;
            op0[t * HH + j] = __float2half_rn(hv0);
            op1[t * HH + j] = __float2half_rn(hv1);
        }
    }
}

// ---------------------------------------------------------------------------
// fp16 tensor-core GEMM (fp32 accumulate): C = A[M,K] @ W[N,K]^T + bias.
// cp.async double-buffered, 2x2 warps, fragment double-buffering.
// ---------------------------------------------------------------------------

__device__ __forceinline__ void cp_async16(uint32_t dst, const void* src, int src_bytes) {
    asm volatile("cp.async.cg.shared.global [%0], [%1], 16, %2;\n"
                 :: "r"(dst), "l"(src), "r"(src_bytes));
}
__device__ __forceinline__ void cp_commit() {
    asm volatile("cp.async.commit_group;\n" ::: "memory");
}
template <int N>
__device__ __forceinline__ void cp_wait() {
    asm volatile("cp.async.wait_group %0;\n" :: "n"(N) : "memory");
}

__device__ __forceinline__ void mma_f16(float (&c)[4], const uint32_t (&a)[4],
                                        const uint32_t (&b)[2]) {
    asm volatile(
        "mma.sync.aligned.m16n8k16.row.col.f32.f16.f16.f32 "
        "{%0,%1,%2,%3}, {%4,%5,%6,%7}, {%8,%9}, {%0,%1,%2,%3};"
        : "+f"(c[0]), "+f"(c[1]), "+f"(c[2]), "+f"(c[3])
        : "r"(a[0]), "r"(a[1]), "r"(a[2]), "r"(a[3]), "r"(b[0]), "r"(b[1]));
}

template <int BM, int BN, bool RELU, bool OUT_HALF>
__global__ __launch_bounds__(128, 2)
void gemm_f16(const __half* __restrict__ A, const __half* __restrict__ W,
              const float* __restrict__ bias, void* __restrict__ Cv,
              int M, int N, int K)
{
    constexpr int BK = 64;
    constexpr int THREADS = 128;
    constexpr int WARPS_M = 2, WARPS_N = 2;
    constexpr int WM = BM / WARPS_M;
    constexpr int WN = BN / WARPS_N;
    constexpr int MT = WM / 16;
    constexpr int NT = WN / 8;
    constexpr int LDW = BK / 2 + 4;

    extern __shared__ uint32_t sm[];
    uint32_t* As = sm;
    uint32_t* Bs = sm + 2 * BM * LDW;

    const int tid  = threadIdx.x;
    const int lane = tid & 31;
    const int warp = tid >> 5;
    const int wm   = warp / WARPS_N;
    const int wn   = warp % WARPS_N;
    const int g    = lane >> 2;
    const int t    = lane & 3;

    const int m0 = blockIdx.y * BM;
    const int n0 = blockIdx.x * BN;

    const uint32_t as_smem = (uint32_t)__cvta_generic_to_shared(As);
    const uint32_t bs_smem = (uint32_t)__cvta_generic_to_shared(Bs);

    float acc[MT][NT][4];
#pragma unroll
    for (int i = 0; i < MT; i++)
#pragma unroll
        for (int j = 0; j < NT; j++)
#pragma unroll
            for (int q = 0; q < 4; q++) acc[i][j][q] = 0.f;

    constexpr int KQ = BK / 8;
    constexpr int A_ITERS = BM * KQ / THREADS;
    constexpr int B_ITERS = BN * KQ / THREADS;

    auto load_tiles = [&](int k0, int stage) {
        const uint32_t a_base = as_smem + (uint32_t)stage * BM * LDW * 4;
        const uint32_t b_base = bs_smem + (uint32_t)stage * BN * LDW * 4;
#pragma unroll
        for (int r = 0; r < A_ITERS; r++) {
            const int idx = tid + r * THREADS;
            const int row = idx / KQ;
            const int kq  = idx % KQ;
            const int kg  = k0 + kq * 8;
            const bool ok = kg < K;
            const __half* src = ok ? &A[(size_t)(m0 + row) * K + kg] : A;
            cp_async16(a_base + (row * LDW + kq * 4) * 4, src, ok ? 16 : 0);
        }
#pragma unroll
        for (int r = 0; r < B_ITERS; r++) {
            const int idx = tid + r * THREADS;
            const int row = idx / KQ;
            const int kq  = idx % KQ;
            const int kg  = k0 + kq * 8;
            const bool ok = (n0 + row) < N && kg < K;
            const __half* src = ok ? &W[(size_t)(n0 + row) * K + kg] : W;
            cp_async16(b_base + (row * LDW + kq * 4) * 4, src, ok ? 16 : 0);
        }
        cp_commit();
    };

    const int nk = (K + BK - 1) / BK;

    load_tiles(0, 0);

    uint32_t af[2][MT][4], bf[2][NT][2];

    for (int it = 0; it < nk; it++) {
        const int cur = it & 1;
        if (it + 1 < nk) {
            load_tiles((it + 1) * BK, (it + 1) & 1);
            cp_wait<1>();
        } else {
            cp_wait<0>();
        }
        __syncthreads();

        const uint32_t* Ac = As + cur * BM * LDW;
        const uint32_t* Bc = Bs + cur * BN * LDW;

        auto ldfrag = [&](int ks, int buf) {
            const int wb = ks * 8;
#pragma unroll
            for (int mt = 0; mt < MT; mt++) {
                const int r = wm * WM + mt * 16 + g;
                af[buf][mt][0] = Ac[(r    ) * LDW + wb + t    ];
                af[buf][mt][1] = Ac[(r + 8) * LDW + wb + t    ];
                af[buf][mt][2] = Ac[(r    ) * LDW + wb + t + 4];
                af[buf][mt][3] = Ac[(r + 8) * LDW + wb + t + 4];
            }
#pragma unroll
            for (int nt = 0; nt < NT; nt++) {
                const int cc = wn * WN + nt * 8 + g;
                bf[buf][nt][0] = Bc[cc * LDW + wb + t    ];
                bf[buf][nt][1] = Bc[cc * LDW + wb + t + 4];
            }
        };

        ldfrag(0, 0);
#pragma unroll
        for (int ks = 0; ks < 4; ks++) {
            const int cb = ks & 1;
            if (ks + 1 < 4)
                ldfrag(ks + 1, cb ^ 1);
#pragma unroll
            for (int mt = 0; mt < MT; mt++)
#pragma unroll
                for (int nt = 0; nt < NT; nt++)
                    mma_f16(acc[mt][nt], af[cb][mt], bf[cb][nt]);
        }
        __syncthreads();
    }

#pragma unroll
    for (int mt = 0; mt < MT; mt++) {
        const int r0 = m0 + wm * WM + mt * 16 + g;
        const int r1 = r0 + 8;
#pragma unroll
        for (int nt = 0; nt < NT; nt++) {
            const int cbase = n0 + wn * WN + nt * 8 + 2 * t;
            if (OUT_HALF) {
                const float bv0 = bias[cbase], bv1 = bias[cbase + 1];
                float v00 = acc[mt][nt][0] + bv0;
                float v01 = acc[mt][nt][1] + bv1;
                float v10 = acc[mt][nt][2] + bv0;
                float v11 = acc[mt][nt][3] + bv1;
                if (RELU) {
                    v00 = fmaxf(v00, 0.f); v01 = fmaxf(v01, 0.f);
                    v10 = fmaxf(v10, 0.f); v11 = fmaxf(v11, 0.f);
                }
                __half2* C = (__half2*)Cv;
                C[((size_t)r0 * N + cbase) >> 1] = __floats2half2_rn(v00, v01);
                C[((size_t)r1 * N + cbase) >> 1] = __floats2half2_rn(v10, v11);
            } else {
                float* C = (float*)Cv;
#pragma unroll
                for (int q = 0; q < 2; q++) {
                    const int cn = cbase + q;
                    if (cn < N) {
                        const float bv = bias[cn];
                        float v0 = acc[mt][nt][q] + bv;
                        float v1 = acc[mt][nt][2 + q] + bv;
                        if (RELU) { v0 = fmaxf(v0, 0.f); v1 = fmaxf(v1, 0.f); }
                        C[(size_t)r0 * N + cn] = v0;
                        C[(size_t)r1 * N + cn] = v1;
                    }
                }
            }
        }
    }
}

// ---------------------------------------------------------------------------
extern "C" void kernel_launch(void* const* d_in, const int* in_sizes, int n_in,
                              void* d_out, int out_size)
{
    const float* x    = (const float*)d_in[0];
    const float* Wih1 = (const float*)d_in[1];
    const float* Whh1 = (const float*)d_in[2];
    const float* bih1 = (const float*)d_in[3];
    const float* bhh1 = (const float*)d_in[4];
    const float* Wih2 = (const float*)d_in[5];
    const float* Whh2 = (const float*)d_in[6];
    const float* bih2 = (const float*)d_in[7];
    const float* bhh2 = (const float*)d_in[8];
    const float* Wih3 = (const float*)d_in[9];
    const float* Whh3 = (const float*)d_in[10];
    const float* bih3 = (const float*)d_in[11];
    const float* bhh3 = (const float*)d_in[12];
    const float* W1   = (const float*)d_in[13];
    const float* b1   = (const float*)d_in[14];
    const float* W2   = (const float*)d_in[15];
    const float* b2   = (const float*)d_in[16];
    const float* W3   = (const float*)d_in[17];
    const float* b3   = (const float*)d_in[18];
    float* out = (float*)d_out;

    __half *lstm_h, *a1h, *a2h, *w1h, *w2h, *w3h;
    cudaGetSymbolAddress((void**)&lstm_h, g_lstm_h);
    cudaGetSymbolAddress((void**)&a1h, g_a1h);
    cudaGetSymbolAddress((void**)&a2h, g_a2h);
    cudaGetSymbolAddress((void**)&w1h, g_w1h);
    cudaGetSymbolAddress((void**)&w2h, g_w2h);
    cudaGetSymbolAddress((void**)&w3h, g_w3h);

    constexpr int LDW = 36;
    constexpr int SMEM_128 = (2 * 128 * LDW + 2 * 128 * LDW) * 4;  // 73728
    constexpr int SMEM_64  = (2 * 128 * LDW + 2 * 64 * LDW) * 4;   // 55296

    static bool attr_done = false;
    if (!attr_done) {
        cudaFuncSetAttribute(gemm_f16<128, 128, true, true>,
                             cudaFuncAttributeMaxDynamicSharedMemorySize, SMEM_128);
        cudaFuncSetAttribute(gemm_f16<128, 64, true, true>,
                             cudaFuncAttributeMaxDynamicSharedMemorySize, SMEM_64);
        cudaFuncSetAttribute(gemm_f16<128, 64, false, false>,
                             cudaFuncAttributeMaxDynamicSharedMemorySize, SMEM_64);
        attr_done = true;
    }

    // 0) pre-convert weights to fp16
    {
        const int n4_1 = N1 * D_LSTM / 4;
        const int n4_2 = N2 * N1 / 4;
        const int n4_3 = N3 * N2 / 4;
        cvt_w_half<<<(n4_1 + 255) / 256, 256>>>((const float4*)W1, (__half2*)w1h, n4_1);
        cvt_w_half<<<(n4_2 + 255) / 256, 256>>>((const float4*)W2, (__half2*)w2h, n4_2);
        cvt_w_half<<<(n4_3 + 255) / 256, 256>>>((const float4*)W3, (__half2*)w3h, n4_3);
    }

    // 1) fused 3-layer LSTM (layer-skewed wavefront), 32-thr blocks, 512 blocks
    lstm3_kernel<<<BATCH / 4, 32>>>(x,
        Wih1, Whh1, bih1, bhh1,
        Wih2, Whh2, bih2, bhh2,
        Wih3, Whh3, bih3, bhh3,
        lstm_h);

    // 2) MLP head (fp16 mma, fp32 accumulate)
    {   // [2048,4872] x [4096,4872]^T -> relu -> [2048,4096] fp16
        dim3 grid(N1 / 128, BATCH / 128);
        gemm_f16<128, 128, true, true><<<grid, 128, SMEM_128>>>(
            lstm_h, w1h, b1, a1h, BATCH, N1, D_LSTM);
    }
    {   // [2048,4096] x [1024,4096]^T -> relu -> [2048,1024] fp16
        dim3 grid(N2 / 64, BATCH / 128);
        gemm_f16<128, 64, true, true><<<grid, 128, SMEM_64>>>(
            a1h, w2h, b2, a2h, BATCH, N2, N1);
    }
    {   // [2048,1024] x [609,1024]^T -> [2048,609] fp32
        dim3 grid((N3 + 63) / 64, BATCH / 128);
        gemm_f16<128, 64, false, false><<<grid, 128, SMEM_64>>>(
            a2h, w3h, b3, out, BATCH, N3, N2);
    }
}